// round 1
// baseline (speedup 1.0000x reference)
#include <cuda_runtime.h>
#include <math.h>

#define BB 2
#define HH 192
#define WW 192
#define HQ 384
#define EPSF 1e-7f

// ---------------- scratch (device globals: allocation-free) ----------------
__device__ float g_a4 [BB*96*96*32];
__device__ float g_a32[BB*24*24*32];
__device__ float g_X  [BB*HH*WW*96];   // concat input to conv3x3
__device__ float g_aspp[BB*HH*WW*96];  // conv3x3 output

// ---------------- conv1x1 + ReLU (Cout = 32) ----------------
__global__ void conv1x1_relu_k(const float* __restrict__ in,
                               const float* __restrict__ w,
                               const float* __restrict__ bias,
                               float* __restrict__ out,
                               int npix, int Cin, int ostride, int coff) {
    __shared__ float sw[160*32];
    __shared__ float sb[32];
    int tid = threadIdx.x;
    for (int i = tid; i < Cin*32; i += blockDim.x) sw[i] = w[i];
    if (tid < 32) sb[tid] = bias[tid];
    __syncthreads();
    int px = blockIdx.x * 32 + (tid >> 3);   // 8 threads per pixel
    int co = (tid & 7) * 4;                  // 4 consecutive out-channels
    if (px >= npix) return;
    const float* ip = in + (long)px * Cin;
    float a0 = 0.f, a1 = 0.f, a2 = 0.f, a3 = 0.f;
    for (int ci = 0; ci < Cin; ci++) {
        float xv = ip[ci];
        float4 wv = *(const float4*)&sw[ci*32 + co];
        a0 = fmaf(xv, wv.x, a0);
        a1 = fmaf(xv, wv.y, a1);
        a2 = fmaf(xv, wv.z, a2);
        a3 = fmaf(xv, wv.w, a3);
    }
    float* op = out + (long)px * ostride + coff + co;
    op[0] = fmaxf(a0 + sb[co+0], 0.f);
    op[1] = fmaxf(a1 + sb[co+1], 0.f);
    op[2] = fmaxf(a2 + sb[co+2], 0.f);
    op[3] = fmaxf(a3 + sb[co+3], 0.f);
}

// ---------------- bilinear upsample a4(96x96) & a32(24x24) -> X[.., 32..95] ----------------
__global__ void upsample_k() {
    int idx = blockIdx.x * blockDim.x + threadIdx.x;
    const int total = BB*HH*WW*64;
    if (idx >= total) return;
    int ch2 = idx & 63;
    int p = idx >> 6;
    int x = p % WW;
    int y = (p / WW) % HH;
    int b = p / (WW*HH);

    int S, ch;
    const float* src;
    if (ch2 < 32) { S = 96; ch = ch2;       src = g_a4;  }
    else          { S = 24; ch = ch2 - 32;  src = g_a32; }
    float scale = (float)S / (float)HH;   // 0.5 or 0.125 (exact)
    float fy = (y + 0.5f) * scale - 0.5f;
    float fx = (x + 0.5f) * scale - 0.5f;
    int y0 = (int)floorf(fy); float ty = fy - (float)y0;
    int x0 = (int)floorf(fx); float tx = fx - (float)x0;
    int y0c = max(y0, 0), y1c = min(y0 + 1, S - 1);
    int x0c = max(x0, 0), x1c = min(x0 + 1, S - 1);
    const float* base = src + (long)b * S * S * 32;
    float v00 = base[(y0c*S + x0c)*32 + ch];
    float v01 = base[(y0c*S + x1c)*32 + ch];
    float v10 = base[(y1c*S + x0c)*32 + ch];
    float v11 = base[(y1c*S + x1c)*32 + ch];
    float v = (1.f-ty)*((1.f-tx)*v00 + tx*v01) + ty*((1.f-tx)*v10 + tx*v11);
    g_X[((long)(b*HH + y)*WW + x)*96 + 32 + ch2] = v;
}

// ---------------- conv3x3 (96 -> 96) + ReLU ----------------
// block: 16x16 pixel tile, 384 threads. thread = 8 px x 8 co micro-tile.
// smem per ci-chunk(16): input tile [16ci][18][18] + weights [9][16ci][96co]
__global__ void __launch_bounds__(384, 1)
conv3x3_k(const float* __restrict__ wf, const float* __restrict__ bf) {
    extern __shared__ float cs[];
    float* tile = cs;                 // 16*18*18 = 5184 floats
    float* ws   = cs + 16*18*18;      // 9*16*96 = 13824 floats

    int t   = threadIdx.x;
    int bx  = blockIdx.x, by = blockIdx.y, b = blockIdx.z;
    int cog = t >> 5;                 // 0..11 -> co group of 8
    int pxg = t & 31;
    int row = pxg >> 1;               // 0..15
    int xh  = pxg & 1;                // half-row: pixels xh*8..xh*8+7

    float acc[8][8];
    #pragma unroll
    for (int i = 0; i < 8; i++)
        #pragma unroll
        for (int j = 0; j < 8; j++) acc[i][j] = 0.f;

    #pragma unroll 1
    for (int c0 = 0; c0 < 96; c0 += 16) {
        __syncthreads();
        // load input tile chunk (zero pad)
        for (int idx = t; idx < 18*18*16; idx += 384) {
            int ci = idx & 15;
            int p  = idx >> 4;
            int xx = p % 18, yy = p / 18;
            int gy = by*16 + yy - 1, gx = bx*16 + xx - 1;
            float v = 0.f;
            if (gy >= 0 && gy < HH && gx >= 0 && gx < WW)
                v = g_X[((long)(b*HH + gy)*WW + gx)*96 + c0 + ci];
            tile[(ci*18 + yy)*18 + xx] = v;
        }
        // load weight chunk: ws[k][ci][co] = wf[k][c0+ci][co] (contiguous per k)
        for (int idx = t; idx < 9*16*96; idx += 384) {
            int k = idx / (16*96);
            int r = idx - k*(16*96);
            ws[k*16*96 + r] = wf[(k*96 + c0)*96 + r];
        }
        __syncthreads();

        #pragma unroll 1
        for (int ky = 0; ky < 3; ky++) {
            #pragma unroll 1
            for (int ci = 0; ci < 16; ci++) {
                const float* tr = &tile[(ci*18 + row + ky)*18 + xh*8];
                float xv[10];
                #pragma unroll
                for (int q = 0; q < 10; q++) xv[q] = tr[q];
                #pragma unroll
                for (int kx = 0; kx < 3; kx++) {
                    const float4* wp = (const float4*)&ws[((ky*3 + kx)*16 + ci)*96 + cog*8];
                    float4 w0 = wp[0], w1 = wp[1];
                    #pragma unroll
                    for (int i = 0; i < 8; i++) {
                        float x = xv[i + kx];
                        acc[i][0] = fmaf(x, w0.x, acc[i][0]);
                        acc[i][1] = fmaf(x, w0.y, acc[i][1]);
                        acc[i][2] = fmaf(x, w0.z, acc[i][2]);
                        acc[i][3] = fmaf(x, w0.w, acc[i][3]);
                        acc[i][4] = fmaf(x, w1.x, acc[i][4]);
                        acc[i][5] = fmaf(x, w1.y, acc[i][5]);
                        acc[i][6] = fmaf(x, w1.z, acc[i][6]);
                        acc[i][7] = fmaf(x, w1.w, acc[i][7]);
                    }
                }
            }
        }
    }
    // epilogue: bias + relu
    float bv[8];
    #pragma unroll
    for (int j = 0; j < 8; j++) bv[j] = bf[cog*8 + j];
    int gy = by*16 + row;
    #pragma unroll
    for (int i = 0; i < 8; i++) {
        int gx = bx*16 + xh*8 + i;
        float* op = &g_aspp[((long)(b*HH + gy)*WW + gx)*96 + cog*8];
        #pragma unroll
        for (int j = 0; j < 8; j++)
            op[j] = fmaxf(acc[i][j] + bv[j], 0.f);
    }
}

// ---------------- query kernel: gather + MLP(102->64->64->1) + blend ----------------
// persistent blocks; per tile: 32 queries x 4 corners = 128 rows.
// shared (floats): sW0 6528 | sB0 64 | sW1 4096 | sB1 64 | sW2 64 | sA 128x104 | sArea 128 | sPred 128 | sPartial 256 | sOff(int) 128
#define QS_W0 0
#define QS_B0 6528
#define QS_W1 6592
#define QS_B1 10688
#define QS_W2 10752
#define QS_A  10816
#define QS_AREA (10816 + 13312)
#define QS_PRED (QS_AREA + 128)
#define QS_PART (QS_PRED + 128)
#define QS_OFF  (QS_PART + 256)
#define QS_TOTAL (QS_OFF + 128)       // 24768 floats = 99072 bytes

__global__ void __launch_bounds__(256, 2)
query_k(const float* __restrict__ coords, const float* __restrict__ cells,
        const float* __restrict__ mw0, const float* __restrict__ mb0,
        const float* __restrict__ mw1, const float* __restrict__ mb1,
        const float* __restrict__ mw2, const float* __restrict__ mb2,
        float* __restrict__ out) {
    extern __shared__ float qs[];
    float* sW0 = qs + QS_W0;
    float* sB0 = qs + QS_B0;
    float* sW1 = qs + QS_W1;
    float* sB1 = qs + QS_B1;
    float* sW2 = qs + QS_W2;
    float* sA  = qs + QS_A;
    float* sArea = qs + QS_AREA;
    float* sPred = qs + QS_PRED;
    float* sPart = qs + QS_PART;
    int*   sOff  = (int*)(qs + QS_OFF);
    __shared__ float sB2;

    int t = threadIdx.x;
    for (int i = t; i < 6528; i += 256) sW0[i] = mw0[i];
    for (int i = t; i < 4096; i += 256) sW1[i] = mw1[i];
    if (t < 64) { sB0[t] = mb0[t]; sB1[t] = mb1[t]; sW2[t] = mw2[t]; }
    if (t == 0) sB2 = mb2[0];
    __syncthreads();

    const int NT = (BB*HQ*HQ) / 32;   // 9216 tiles
    int rg = t >> 4;   // row group: rows rg*8 .. rg*8+7
    int cg = t & 15;   // col group: cols cg*4 .. cg*4+3

    for (int tileI = blockIdx.x; tileI < NT; tileI += gridDim.x) {
        // ---- Phase A: per-row meta ----
        if (t < 128) {
            int row = t;
            int q = tileI*32 + (row >> 2);
            int corner = row & 3;
            int b = q / (HQ*HQ);
            float cy = coords[q*2 + 0], cx = coords[q*2 + 1];
            float cly = cells[q*2 + 0], clx = cells[q*2 + 1];
            float vy = (corner & 2) ? 1.f : -1.f;
            float vx = (corner & 1) ? 1.f : -1.f;
            float yc = cy + vy * (1.f/(float)HH) + EPSF;
            float xc = cx + vx * (1.f/(float)WW) + EPSF;
            yc = fminf(fmaxf(yc, -1.f + EPSF), 1.f - EPSF);
            xc = fminf(fmaxf(xc, -1.f + EPSF), 1.f - EPSF);
            int iy = (int)rintf((yc + 1.f) * ((float)HH * 0.5f) - 0.5f);
            int ix = (int)rintf((xc + 1.f) * ((float)WW * 0.5f) - 0.5f);
            iy = min(max(iy, 0), HH - 1);
            ix = min(max(ix, 0), WW - 1);
            float sy = (((float)iy + 0.5f) / (float)HH) * 2.f - 1.f;
            float sx = (((float)ix + 0.5f) / (float)WW) * 2.f - 1.f;
            float ry = (cy - sy) * (float)HH;
            float rx = (cx - sx) * (float)WW;
            sA[row*104 +  96] = ry;
            sA[row*104 +  97] = rx;
            sA[row*104 +  98] = cy;
            sA[row*104 +  99] = cx;
            sA[row*104 + 100] = cly * (float)HH;
            sA[row*104 + 101] = clx * (float)WW;
            sArea[row] = fabsf(ry * rx) + EPSF;
            sOff[row] = ((b*HH + iy)*WW + ix) * 96;
        }
        __syncthreads();
        // ---- Phase B: gather features (96 floats per row) ----
        {
            int row = t >> 1, half = t & 1;
            const float4* src = (const float4*)(g_aspp + sOff[row] + half*48);
            float4* dst = (float4*)&sA[row*104 + half*48];
            #pragma unroll
            for (int i = 0; i < 12; i++) dst[i] = src[i];
        }
        __syncthreads();

        // ---- GEMM1: [128x102] @ [102x64] ----
        float acc[8][4];
        #pragma unroll
        for (int i = 0; i < 8; i++)
            #pragma unroll
            for (int j = 0; j < 4; j++) acc[i][j] = 0.f;
        #pragma unroll 1
        for (int k2 = 0; k2 < 51; k2++) {
            int k = k2*2;
            float4 b0 = *(const float4*)&sW0[k*64 + cg*4];
            float4 b1 = *(const float4*)&sW0[(k+1)*64 + cg*4];
            #pragma unroll
            for (int i = 0; i < 8; i++) {
                float2 a = *(const float2*)&sA[(rg*8 + i)*104 + k];
                acc[i][0] = fmaf(a.y, b1.x, fmaf(a.x, b0.x, acc[i][0]));
                acc[i][1] = fmaf(a.y, b1.y, fmaf(a.x, b0.y, acc[i][1]));
                acc[i][2] = fmaf(a.y, b1.z, fmaf(a.x, b0.z, acc[i][2]));
                acc[i][3] = fmaf(a.y, b1.w, fmaf(a.x, b0.w, acc[i][3]));
            }
        }
        __syncthreads();
        #pragma unroll
        for (int i = 0; i < 8; i++)
            #pragma unroll
            for (int j = 0; j < 4; j++)
                sA[(rg*8 + i)*104 + cg*4 + j] = fmaxf(acc[i][j] + sB0[cg*4 + j], 0.f);
        __syncthreads();

        // ---- GEMM2: [128x64] @ [64x64] ----
        #pragma unroll
        for (int i = 0; i < 8; i++)
            #pragma unroll
            for (int j = 0; j < 4; j++) acc[i][j] = 0.f;
        #pragma unroll 1
        for (int k2 = 0; k2 < 32; k2++) {
            int k = k2*2;
            float4 b0 = *(const float4*)&sW1[k*64 + cg*4];
            float4 b1 = *(const float4*)&sW1[(k+1)*64 + cg*4];
            #pragma unroll
            for (int i = 0; i < 8; i++) {
                float2 a = *(const float2*)&sA[(rg*8 + i)*104 + k];
                acc[i][0] = fmaf(a.y, b1.x, fmaf(a.x, b0.x, acc[i][0]));
                acc[i][1] = fmaf(a.y, b1.y, fmaf(a.x, b0.y, acc[i][1]));
                acc[i][2] = fmaf(a.y, b1.z, fmaf(a.x, b0.z, acc[i][2]));
                acc[i][3] = fmaf(a.y, b1.w, fmaf(a.x, b0.w, acc[i][3]));
            }
        }
        __syncthreads();
        #pragma unroll
        for (int i = 0; i < 8; i++)
            #pragma unroll
            for (int j = 0; j < 4; j++)
                sA[(rg*8 + i)*104 + cg*4 + j] = fmaxf(acc[i][j] + sB1[cg*4 + j], 0.f);
        __syncthreads();

        // ---- GEMM3: [128x64] @ [64x1] ----
        {
            int row = t >> 1, half = t & 1;
            float s = 0.f;
            #pragma unroll
            for (int c = 0; c < 32; c++)
                s = fmaf(sA[row*104 + half*32 + c], sW2[half*32 + c], s);
            sPart[t] = s;
        }
        __syncthreads();
        if (t < 128) sPred[t] = sPart[2*t] + sPart[2*t + 1] + sB2;
        __syncthreads();
        // ---- blend corners (pred c pairs with area of corner 3-c) ----
        if (t < 32) {
            int q = tileI*32 + t;
            float num = 0.f, den = 0.f;
            #pragma unroll
            for (int c = 0; c < 4; c++) {
                float ar = sArea[t*4 + (3 - c)];
                num = fmaf(sPred[t*4 + c], ar, num);
                den += ar;
            }
            out[q] = num / den;
        }
        __syncthreads();
    }
}

// ---------------- launch ----------------
extern "C" void kernel_launch(void* const* d_in, const int* in_sizes, int n_in,
                              void* d_out, int out_size) {
    const float* feats2  = (const float*)d_in[0];
    const float* feats4  = (const float*)d_in[1];
    const float* feats32 = (const float*)d_in[2];
    const float* coords  = (const float*)d_in[3];
    const float* cells   = (const float*)d_in[4];
    const float* w2  = (const float*)d_in[5];
    const float* b2  = (const float*)d_in[6];
    const float* w4  = (const float*)d_in[7];
    const float* b4  = (const float*)d_in[8];
    const float* w32 = (const float*)d_in[9];
    const float* b32 = (const float*)d_in[10];
    const float* wf  = (const float*)d_in[11];
    const float* bf  = (const float*)d_in[12];
    const float* mw0 = (const float*)d_in[13];
    const float* mb0 = (const float*)d_in[14];
    const float* mw1 = (const float*)d_in[15];
    const float* mb1 = (const float*)d_in[16];
    const float* mw2 = (const float*)d_in[17];
    const float* mb2 = (const float*)d_in[18];
    float* out = (float*)d_out;

    float *pX, *pA4, *pA32;
    cudaGetSymbolAddress((void**)&pX,  g_X);
    cudaGetSymbolAddress((void**)&pA4, g_a4);
    cudaGetSymbolAddress((void**)&pA32, g_a32);

    cudaFuncSetAttribute(conv3x3_k, cudaFuncAttributeMaxDynamicSharedMemorySize, (16*18*18 + 9*16*96) * 4);
    cudaFuncSetAttribute(query_k,  cudaFuncAttributeMaxDynamicSharedMemorySize, QS_TOTAL * 4);

    // conv1x1 heads
    {
        int npix = BB*HH*WW;   // 73728
        conv1x1_relu_k<<<(npix + 31)/32, 256>>>(feats2, w2, b2, pX, npix, 64, 96, 0);
    }
    {
        int npix = BB*96*96;   // 18432
        conv1x1_relu_k<<<(npix + 31)/32, 256>>>(feats4, w4, b4, pA4, npix, 96, 32, 0);
    }
    {
        int npix = BB*24*24;   // 1152
        conv1x1_relu_k<<<(npix + 31)/32, 256>>>(feats32, w32, b32, pA32, npix, 160, 32, 0);
    }
    // upsample + concat
    {
        int total = BB*HH*WW*64;
        upsample_k<<<(total + 255)/256, 256>>>();
    }
    // conv3x3 fuse
    {
        dim3 grid(WW/16, HH/16, BB);
        conv3x3_k<<<grid, 384, (16*18*18 + 9*16*96) * 4>>>(wf, bf);
    }
    // query MLP (persistent)
    {
        query_k<<<296, 256, QS_TOTAL * 4>>>(coords, cells, mw0, mb0, mw1, mb1, mw2, mb2, out);
    }
}